// round 16
// baseline (speedup 1.0000x reference)
#include <cuda_runtime.h>
#include <cstdint>

// Blocked Hadamard transform, BLOCK = 256 = 4^4.
// H4 = ones(4) - 2*antidiag ; H = kron(H4 x4) / 16.
// In-block index i = i0 + 4*i1 + 16*i2 + 64*i3 (base-4 digits).
//
// Converged layout (R9). Warp handles 512 consecutive floats (2 blocks) as
// 4 float4 chunks per thread:
//   idx = 4*lane + e + 128*c,  e in [0,4), c in [0,4)
//   -> i0 = e (register-local), i1 = lane[1:0], i2 = lane[3:2],
//      i3 = (c&1)<<1 | lane[4], block = c>>1.
// All global accesses are warp-contiguous LDG.128/STG.128 (512B per inst),
// all 4 loads front-batched (MLP_p1 = 4).
//
// Shuffle floor (proven): coalescing pins addr bits 2-6 to lanes at both IO
// ends, so i1/i2 are irreducibly lane^2 (2 SHFL/value) and i3 is split
// (0.5 SHFL/value): 72 SHFL/thread. Scheduling: chunks are processed in
// dependency order (pair 0 = chunks 0,1 fully retired before pair 1 is
// touched) so the first STG issues ~2 shuffle-chain depths earlier while
// chunks 2,3 loads are still in flight.

__device__ __forceinline__ void h4_local(float4& t)
{
    // Stage i0: H4 within the float4
    float s01 = t.x + t.y, d01 = t.x - t.y;
    float s23 = t.z + t.w, d23 = t.z - t.w;
    t.x = s01 + d23;   //  x0+x1+x2-x3
    t.y = s01 - d23;   //  x0+x1-x2+x3
    t.z = d01 + s23;   //  x0-x1+x2+x3
    t.w = s23 - d01;   // -x0+x1+x2+x3
}

__device__ __forceinline__ float h4_lane_pair(float x, int m1, int m2)
{
    // 2-shuffle identity for a lane^2 digit with bits (m1, 2*m1=m2):
    // y = (x + shfl(x,m1)) + shfl(x - shfl(x,m1), m2)
    float a  = __shfl_xor_sync(0xffffffffu, x, m1);
    float s  = x + a;
    float d  = x - a;
    float d2 = __shfl_xor_sync(0xffffffffu, d, m2);
    return s + d2;
}

__device__ __forceinline__ void finish_chunk(float4& t)
{
    // Stage i1 (lane bits [1:0]) then i2 (lane bits [3:2]), fold 1/16.
    float* f = reinterpret_cast<float*>(&t);
    #pragma unroll
    for (int e = 0; e < 4; e++)
        f[e] = h4_lane_pair(f[e], 1, 2);
    #pragma unroll
    for (int e = 0; e < 4; e++)
        f[e] = h4_lane_pair(f[e], 4, 8) * 0.0625f;
}

__device__ __forceinline__ void i3_split_pair(float4& A, float4& B)
{
    // Stage i3: split digit (low bit = lane bit 4, high bit = chunk bit).
    // ONE shuffle per element pair on the difference:
    //   s = A+B; d = A-B; ds = shfl_xor(d,16); A' = s+ds; B' = s-ds
    float* a = reinterpret_cast<float*>(&A);
    float* b = reinterpret_cast<float*>(&B);
    #pragma unroll
    for (int e = 0; e < 4; e++) {
        float s = a[e] + b[e];
        float d = a[e] - b[e];
        float ds = __shfl_xor_sync(0xffffffffu, d, 16);
        a[e] = s + ds;
        b[e] = s - ds;
    }
}

__global__ void __launch_bounds__(256) hadamard256_kernel(
    const float* __restrict__ x, float* __restrict__ out)
{
    const unsigned warp_global = blockIdx.x * 8u + (threadIdx.x >> 5);
    const unsigned lane = threadIdx.x & 31u;
    // base in float4 units; warp accesses are contiguous 512B per instruction
    const size_t base4 = (size_t)warp_global * 128u + lane;

    const float4* xp = reinterpret_cast<const float4*>(x) + base4;
    float4* op = reinterpret_cast<float4*>(out) + base4;

    // Front-batch all 4 loads (keep MLP_p1 = 4).
    float4 v0 = __ldcs(xp);
    float4 v1 = __ldcs(xp + 32);
    float4 v2 = __ldcs(xp + 64);
    float4 v3 = __ldcs(xp + 96);

    // ---- Pair 0 (chunks 0,1): retire fully while chunks 2,3 are in flight ----
    h4_local(v0);
    h4_local(v1);
    i3_split_pair(v0, v1);
    finish_chunk(v0);
    __stcs(op, v0);
    finish_chunk(v1);
    __stcs(op + 32, v1);

    // ---- Pair 1 (chunks 2,3) ----
    h4_local(v2);
    h4_local(v3);
    i3_split_pair(v2, v3);
    finish_chunk(v2);
    __stcs(op + 64, v2);
    finish_chunk(v3);
    __stcs(op + 96, v3);
}

extern "C" void kernel_launch(void* const* d_in, const int* in_sizes, int n_in,
                              void* d_out, int out_size)
{
    const float* x = (const float*)d_in[0];
    float* out = (float*)d_out;

    // out_size = 2*4096*8192 = 67,108,864 floats.
    // One warp handles 512 floats; 8 warps (256 threads) per CTA -> 4096 floats/CTA.
    const long long n = (long long)out_size;
    const int cta_elems = 4096;
    const int grid = (int)(n / cta_elems);   // 16384, exact

    hadamard256_kernel<<<grid, 256>>>(x, out);
}

// round 17
// speedup vs baseline: 1.0004x; 1.0004x over previous
#include <cuda_runtime.h>
#include <cstdint>

// Blocked Hadamard transform, BLOCK = 256 = 4^4.
// H4 = ones(4) - 2*antidiag ; H = kron(H4 x4) / 16.
// In-block index i = i0 + 4*i1 + 16*i2 + 64*i3 (base-4 digits).
//
// 256-bit IO variant (Blackwell ld/st.global.v8.f32). Warp tile = 512
// consecutive floats (2 blocks); thread owns 8 consecutive floats per chunk,
// 2 chunks at float offsets {0, 256}:
//   idx = 8*lane + e + 256*c,  e in [0,8), c in [0,2)
// Address-bit map: e -> bits 0..2 (local), lane -> bits 3..7, c -> bit 8
// (block separator). Digits:
//   i0 = bits{0,1} local            -> in-register H4 (free)
//   i1 = bits{2,3} split            -> 1-shuffle butterfly, mask 1
//   i2 = bits{4,5} lane^2           -> 2-shuffle identity, masks (2,4)
//   i3 = bits{6,7} lane^2           -> 2-shuffle identity, masks (8,16)
// 72 SHFL/thread (the proven floor). Every global access is one warp-
// contiguous 1KB request (32B per lane), halving memory instruction count.
//
// Split-digit butterfly (local pair A=d0:0, B=d0:1; lane bit = d1, mask m):
//   s=A+B; d=A-B; ds=shfl_xor(d,m); A'=s+ds; B'=s-ds   (valid for both
//   lane parities; orientation of which bit is local does not matter).

__device__ __forceinline__ void ldg256(const float* __restrict__ p, float* r)
{
    asm volatile("ld.global.v8.f32 {%0,%1,%2,%3,%4,%5,%6,%7}, [%8];"
                 : "=f"(r[0]), "=f"(r[1]), "=f"(r[2]), "=f"(r[3]),
                   "=f"(r[4]), "=f"(r[5]), "=f"(r[6]), "=f"(r[7])
                 : "l"(p));
}

__device__ __forceinline__ void stg256(float* __restrict__ p, const float* r)
{
    asm volatile("st.global.v8.f32 [%0], {%1,%2,%3,%4,%5,%6,%7,%8};"
                 :: "l"(p),
                    "f"(r[0]), "f"(r[1]), "f"(r[2]), "f"(r[3]),
                    "f"(r[4]), "f"(r[5]), "f"(r[6]), "f"(r[7])
                 : "memory");
}

__device__ __forceinline__ float h4_lane_pair(float x, int m1, int m2)
{
    // 2-shuffle identity for a lane^2 digit with bits (m1, m2=2*m1):
    // y = (x + shfl(x,m1)) + shfl(x - shfl(x,m1), m2)
    float a  = __shfl_xor_sync(0xffffffffu, x, m1);
    float s  = x + a;
    float d  = x - a;
    float d2 = __shfl_xor_sync(0xffffffffu, d, m2);
    return s + d2;
}

__device__ __forceinline__ void process_chunk(float* f)
{
    // ---- Stage i0: local H4 over e[1:0], groups {0..3} and {4..7} ----
    #pragma unroll
    for (int g = 0; g < 2; g++) {
        float x0 = f[4*g+0], x1 = f[4*g+1], x2 = f[4*g+2], x3 = f[4*g+3];
        float s01 = x0 + x1, d01 = x0 - x1;
        float s23 = x2 + x3, d23 = x2 - x3;
        f[4*g+0] = s01 + d23;   //  x0+x1+x2-x3
        f[4*g+1] = s01 - d23;   //  x0+x1-x2+x3
        f[4*g+2] = d01 + s23;   //  x0-x1+x2+x3
        f[4*g+3] = s23 - d01;   // -x0+x1+x2+x3
    }

    // ---- Stage i1: split digit (local bit e[2], lane bit mask 1) ----
    #pragma unroll
    for (int e = 0; e < 4; e++) {
        float s = f[e] + f[e + 4];
        float d = f[e] - f[e + 4];
        float ds = __shfl_xor_sync(0xffffffffu, d, 1);
        f[e]     = s + ds;
        f[e + 4] = s - ds;
    }

    // ---- Stage i2: lane^2, masks (2,4) ----
    #pragma unroll
    for (int e = 0; e < 8; e++)
        f[e] = h4_lane_pair(f[e], 2, 4);

    // ---- Stage i3: lane^2, masks (8,16); fold 1/16 ----
    #pragma unroll
    for (int e = 0; e < 8; e++)
        f[e] = h4_lane_pair(f[e], 8, 16) * 0.0625f;
}

__global__ void __launch_bounds__(256) hadamard256_kernel(
    const float* __restrict__ x, float* __restrict__ out)
{
    const unsigned warp_global = blockIdx.x * 8u + (threadIdx.x >> 5);
    const unsigned lane = threadIdx.x & 31u;
    const size_t base = (size_t)warp_global * 512u + (size_t)lane * 8u;

    const float* xp = x + base;
    float* op = out + base;

    // Front-batch both 256-bit loads (2KB in flight per warp).
    float f0[8], f1[8];
    ldg256(xp, f0);
    ldg256(xp + 256, f1);

    process_chunk(f0);
    stg256(op, f0);

    process_chunk(f1);
    stg256(op + 256, f1);
}

extern "C" void kernel_launch(void* const* d_in, const int* in_sizes, int n_in,
                              void* d_out, int out_size)
{
    const float* x = (const float*)d_in[0];
    float* out = (float*)d_out;

    // out_size = 2*4096*8192 = 67,108,864 floats.
    // One warp handles 512 floats; 8 warps (256 threads) per CTA -> 4096 floats/CTA.
    const long long n = (long long)out_size;
    const int cta_elems = 4096;
    const int grid = (int)(n / cta_elems);   // 16384, exact

    hadamard256_kernel<<<grid, 256>>>(x, out);
}